// round 2
// baseline (speedup 1.0000x reference)
#include <cuda_runtime.h>
#include <cstdint>

#define T_STEPS 512
#define BSZ     64
#define NIN     1024
#define HID     1024
#define NOUT    1024

// recurrence partition
#define NC       8     // k-chunks
#define KC       128   // k per chunk (NC*KC = HID)
#define JT       64    // j columns per block
#define RNN_BLOCKS 128 // (HID/JT) * NC = 16*8

// scratch (static __device__ — no allocation allowed)
__device__ float   g_UH[(size_t)T_STEPS * BSZ * HID];   // U, overwritten in place with h_t
__device__ float   g_part[NC * BSZ * HID];              // k-split partials
__device__ unsigned g_cnt;
__device__ unsigned g_gen;

// ---------------------------------------------------------------------------
// GEMM: C[m][n] = sum_k A[m][k] * W[n][k] + bias[n]
// BM=BN=128, BK=8, 256 threads, 8x8 micro-tile. M%128==0, N%128==0, K%8==0.
// ---------------------------------------------------------------------------
__global__ __launch_bounds__(256) void gemm_bias_k(
    const float* __restrict__ A, int lda,
    const float* __restrict__ Wm, int ldw,
    const float* __restrict__ bias,
    float* __restrict__ C, int ldc, int K)
{
    __shared__ float As[8][128];
    __shared__ float Ws[8][128];

    const int m0  = blockIdx.y * 128;
    const int n0  = blockIdx.x * 128;
    const int tid = threadIdx.x;
    const int ty  = tid >> 4;       // 0..15
    const int tx  = tid & 15;       // 0..15
    const int arow = tid >> 1;      // 0..127
    const int ac4  = (tid & 1) * 4; // 0 or 4

    const float* Ag = A  + (size_t)(m0 + arow) * lda + ac4;
    const float* Wg = Wm + (size_t)(n0 + arow) * ldw + ac4;

    float acc[8][8];
#pragma unroll
    for (int i = 0; i < 8; i++)
#pragma unroll
        for (int j = 0; j < 8; j++) acc[i][j] = 0.0f;

    for (int k0 = 0; k0 < K; k0 += 8) {
        float4 av = *reinterpret_cast<const float4*>(Ag + k0);
        float4 wv = *reinterpret_cast<const float4*>(Wg + k0);
        __syncthreads();
        As[ac4 + 0][arow] = av.x;
        As[ac4 + 1][arow] = av.y;
        As[ac4 + 2][arow] = av.z;
        As[ac4 + 3][arow] = av.w;
        Ws[ac4 + 0][arow] = wv.x;
        Ws[ac4 + 1][arow] = wv.y;
        Ws[ac4 + 2][arow] = wv.z;
        Ws[ac4 + 3][arow] = wv.w;
        __syncthreads();
#pragma unroll
        for (int kk = 0; kk < 8; kk++) {
            float a[8], w[8];
            *reinterpret_cast<float4*>(a)     = *reinterpret_cast<const float4*>(&As[kk][ty * 8]);
            *reinterpret_cast<float4*>(a + 4) = *reinterpret_cast<const float4*>(&As[kk][ty * 8 + 4]);
            *reinterpret_cast<float4*>(w)     = *reinterpret_cast<const float4*>(&Ws[kk][tx * 8]);
            *reinterpret_cast<float4*>(w + 4) = *reinterpret_cast<const float4*>(&Ws[kk][tx * 8 + 4]);
#pragma unroll
            for (int i = 0; i < 8; i++)
#pragma unroll
                for (int j = 0; j < 8; j++)
                    acc[i][j] = fmaf(a[i], w[j], acc[i][j]);
        }
    }

    float bs[8];
#pragma unroll
    for (int j = 0; j < 8; j++) bs[j] = bias[n0 + tx * 8 + j];

#pragma unroll
    for (int i = 0; i < 8; i++) {
        float4 v0, v1;
        v0.x = acc[i][0] + bs[0]; v0.y = acc[i][1] + bs[1];
        v0.z = acc[i][2] + bs[2]; v0.w = acc[i][3] + bs[3];
        v1.x = acc[i][4] + bs[4]; v1.y = acc[i][5] + bs[5];
        v1.z = acc[i][6] + bs[6]; v1.w = acc[i][7] + bs[7];
        float* Cp = &C[(size_t)(m0 + ty * 8 + i) * ldc + n0 + tx * 8];
        *reinterpret_cast<float4*>(Cp)     = v0;
        *reinterpret_cast<float4*>(Cp + 4) = v1;
    }
}

// ---------------------------------------------------------------------------
// Grid-wide barrier. Safe: RNN_BLOCKS=128 < 148 SMs -> all blocks co-resident.
// ---------------------------------------------------------------------------
__device__ __forceinline__ void grid_barrier()
{
    __syncthreads();
    if (threadIdx.x == 0) {
        __threadfence();
        unsigned gen = *(volatile unsigned*)&g_gen;
        unsigned arrived = atomicAdd(&g_cnt, 1u);
        if (arrived == gridDim.x - 1) {
            *(volatile unsigned*)&g_cnt = 0u;
            __threadfence();
            atomicAdd(&g_gen, 1u);
        } else {
            while (*(volatile unsigned*)&g_gen == gen) { __nanosleep(64); }
        }
        __threadfence();
    }
    __syncthreads();
}

// ---------------------------------------------------------------------------
// Persistent recurrence: for t in 0..T-1:
//   h_t = tanh(U_t + h_{t-1} @ W_h^T),  written in place over U_t in g_UH.
// Block (c, jt): Phase A computes partial[c][b][j0..j0+63] over k chunk c.
// Phase B (after grid barrier): reduce NC partials + U + tanh.
// W_h slab stays in shared for all 512 steps.
// ---------------------------------------------------------------------------
__global__ __launch_bounds__(256) void rnn_scan_k(
    const float* __restrict__ h0, const float* __restrict__ Wi2h)
{
    extern __shared__ float sm[];
    float* wsh = sm;            // [KC][JT]      : wsh[k*JT + j]
    float* hsh = sm + KC * JT;  // [KC][65] pad  : hsh[k*65 + b]

    const int tid = threadIdx.x;
    const int bid = blockIdx.x;
    const int c   = bid >> 4;    // 0..7  k-chunk
    const int jt  = bid & 15;    // 0..15 j-tile
    const int j0  = jt * JT;
    const int k0  = c * KC;

    // Load this block's W_h slab once (W_h[j][k] = Wi2h[j*2048 + 1024 + k])
    for (int idx = tid; idx < JT * KC; idx += 256) {
        int j = idx / KC, k = idx % KC;
        wsh[k * JT + j] = Wi2h[(size_t)(j0 + j) * (NIN + HID) + NIN + k0 + k];
    }

    const int tb = tid >> 4;  // 0..15 -> b = tb*4 + i
    const int tj = tid & 15;  // 0..15 -> j = j0 + tj*4 + jj

    for (int t = 0; t < T_STEPS; t++) {
        const float* hprev = (t == 0) ? h0 : (g_UH + (size_t)(t - 1) * BSZ * HID);

        // stage h chunk (transposed, padded stride 65 -> conflict-free)
        for (int idx = tid; idx < BSZ * KC; idx += 256) {
            int b = idx >> 7;      // idx / KC
            int k = idx & (KC - 1);
            hsh[k * 65 + b] = hprev[b * HID + k0 + k];
        }
        __syncthreads();  // also covers wsh on t==0

        float acc[4][4];
#pragma unroll
        for (int i = 0; i < 4; i++)
#pragma unroll
            for (int j = 0; j < 4; j++) acc[i][j] = 0.0f;

#pragma unroll 8
        for (int kk = 0; kk < KC; kk++) {
            float a0 = hsh[kk * 65 + tb * 4 + 0];
            float a1 = hsh[kk * 65 + tb * 4 + 1];
            float a2 = hsh[kk * 65 + tb * 4 + 2];
            float a3 = hsh[kk * 65 + tb * 4 + 3];
            float w0 = wsh[kk * JT + tj * 4 + 0];
            float w1 = wsh[kk * JT + tj * 4 + 1];
            float w2 = wsh[kk * JT + tj * 4 + 2];
            float w3 = wsh[kk * JT + tj * 4 + 3];
            acc[0][0] = fmaf(a0, w0, acc[0][0]); acc[0][1] = fmaf(a0, w1, acc[0][1]);
            acc[0][2] = fmaf(a0, w2, acc[0][2]); acc[0][3] = fmaf(a0, w3, acc[0][3]);
            acc[1][0] = fmaf(a1, w0, acc[1][0]); acc[1][1] = fmaf(a1, w1, acc[1][1]);
            acc[1][2] = fmaf(a1, w2, acc[1][2]); acc[1][3] = fmaf(a1, w3, acc[1][3]);
            acc[2][0] = fmaf(a2, w0, acc[2][0]); acc[2][1] = fmaf(a2, w1, acc[2][1]);
            acc[2][2] = fmaf(a2, w2, acc[2][2]); acc[2][3] = fmaf(a2, w3, acc[2][3]);
            acc[3][0] = fmaf(a3, w0, acc[3][0]); acc[3][1] = fmaf(a3, w1, acc[3][1]);
            acc[3][2] = fmaf(a3, w2, acc[3][2]); acc[3][3] = fmaf(a3, w3, acc[3][3]);
        }

        // write partials
#pragma unroll
        for (int i = 0; i < 4; i++) {
            float4 v;
            v.x = acc[i][0]; v.y = acc[i][1]; v.z = acc[i][2]; v.w = acc[i][3];
            *reinterpret_cast<float4*>(
                &g_part[(size_t)(c * BSZ + tb * 4 + i) * HID + j0 + tj * 4]) = v;
        }

        grid_barrier();

        // Phase B: reduce partials + U, tanh, in-place into g_UH[t]
        {
            const int base = bid * ((BSZ * HID) / RNN_BLOCKS);  // bid*512
            for (int l = tid; l < (BSZ * HID) / RNN_BLOCKS; l += 256) {
                int idx = base + l;
                int b = idx >> 10;
                int j = idx & (HID - 1);
                size_t uoff = ((size_t)t * BSZ + b) * HID + j;
                float v = g_UH[uoff];
#pragma unroll
                for (int cc = 0; cc < NC; cc++)
                    v += g_part[(size_t)(cc * BSZ + b) * HID + j];
                g_UH[uoff] = tanhf(v);
            }
        }

        grid_barrier();
    }
}

// ---------------------------------------------------------------------------
extern "C" void kernel_launch(void* const* d_in, const int* in_sizes, int n_in,
                              void* d_out, int out_size)
{
    (void)in_sizes; (void)n_in; (void)out_size;
    const float* x     = (const float*)d_in[0];
    const float* h0    = (const float*)d_in[1];
    const float* W_i2h = (const float*)d_in[2];
    const float* b_i2h = (const float*)d_in[3];
    const float* W_h2o = (const float*)d_in[4];
    const float* b_h2o = (const float*)d_in[5];
    float* out = (float*)d_out;

    float* uh = nullptr;
    cudaGetSymbolAddress((void**)&uh, g_UH);

    // 1) U = X @ Wx^T + b_i2h   (X: 32768x1024, Wx rows stride 2048)
    dim3 g1(NOUT / 128, (T_STEPS * BSZ) / 128);
    gemm_bias_k<<<g1, 256>>>(x, NIN, W_i2h, NIN + HID, b_i2h, uh, HID, NIN);

    // 2) sequential recurrence (persistent kernel, in-place U -> H)
    int smem = (KC * JT + KC * 65) * (int)sizeof(float);  // ~66 KB
    cudaFuncSetAttribute(rnn_scan_k, cudaFuncAttributeMaxDynamicSharedMemorySize, smem);
    rnn_scan_k<<<RNN_BLOCKS, 256, smem>>>(h0, W_i2h);

    // 3) out = H @ W_h2o^T + b_h2o
    gemm_bias_k<<<g1, 256>>>(uh, HID, W_h2o, HID, b_h2o, out, NOUT, HID);
}

// round 5
// speedup vs baseline: 1.1231x; 1.1231x over previous
#include <cuda_runtime.h>
#include <cstdint>

#define T_STEPS 512
#define BSZ     64
#define NIN     1024
#define HID     1024
#define NOUT    1024

// recurrence partition (unchanged — known good)
#define NC       8
#define KC       128
#define JT       64
#define RNN_BLOCKS 128

// scratch
__device__ float   g_UH[(size_t)T_STEPS * BSZ * HID];
__device__ float   g_part[NC * BSZ * HID];
__device__ unsigned g_cnt;
__device__ unsigned g_gen;

// ===========================================================================
// 3xTF32 mma.sync GEMM:  C[m][n] = sum_k A[m][k] * W[n][k] + bias[n]
// CTA 128x128, BK=16, 8 warps (2x4), warp tile 64x32 (4x4 m16n8k8 atoms).
// Register-side hi/lo split, acc += Ah*Wh + Ah*Wl + Al*Wh  (near-fp32).
// cp.async double-buffered smem, padded stride 20 words (conflict-free frags).
// Requires M%128==0, N%128==0, K%16==0.
// ===========================================================================
#define BM 128
#define BN 128
#define BK 16
#define SST 20              // smem row stride in words (16 + 4 pad)

__device__ __forceinline__ void cp_async16(uint32_t smem_addr, const void* gptr) {
    asm volatile("cp.async.cg.shared.global [%0], [%1], 16;"
                 :: "r"(smem_addr), "l"(gptr));
}
__device__ __forceinline__ uint32_t smem_u32(const void* p) {
    uint32_t a;
    asm("{ .reg .u64 t; cvta.to.shared.u64 t, %1; cvt.u32.u64 %0, t; }"
        : "=r"(a) : "l"(p));
    return a;
}
__device__ __forceinline__ uint32_t f2tf32(float v) {
    uint32_t r;
    asm("cvt.rna.tf32.f32 %0, %1;" : "=r"(r) : "f"(v));
    return r;
}
// hi/lo split: hi = tf32(x); lo = tf32(x - hi)
__device__ __forceinline__ void tf32_split(float x, uint32_t& hi, uint32_t& lo) {
    hi = f2tf32(x);
    lo = f2tf32(x - __uint_as_float(hi));
}
__device__ __forceinline__ void mma_tf32(
    float& d0, float& d1, float& d2, float& d3,
    uint32_t a0, uint32_t a1, uint32_t a2, uint32_t a3,
    uint32_t b0, uint32_t b1)
{
    asm volatile(
        "mma.sync.aligned.m16n8k8.row.col.f32.tf32.tf32.f32 "
        "{%0,%1,%2,%3}, {%4,%5,%6,%7}, {%8,%9}, {%0,%1,%2,%3};"
        : "+f"(d0), "+f"(d1), "+f"(d2), "+f"(d3)
        : "r"(a0), "r"(a1), "r"(a2), "r"(a3), "r"(b0), "r"(b1));
}

__global__ __launch_bounds__(256) void gemm_mma_k(
    const float* __restrict__ A, int lda,
    const float* __restrict__ Wm, int ldw,
    const float* __restrict__ bias,
    float* __restrict__ C, int ldc, int K)
{
    __shared__ float As[2][BM * SST];
    __shared__ float Ws[2][BN * SST];

    const int tid = threadIdx.x;
    const int wid = tid >> 5;
    const int lane = tid & 31;
    const int m0 = blockIdx.y * BM;
    const int n0 = blockIdx.x * BN;

    const int warp_m = (wid >> 2) * 64;   // 0 or 64
    const int warp_n = (wid & 3) * 32;    // 0,32,64,96

    // loader mapping: row = tid>>1 (0..127), two 16B chunks at (tid&1)*8 floats
    const int lrow = tid >> 1;
    const int lc   = (tid & 1) * 8;
    const float* Ag = A  + (size_t)(m0 + lrow) * lda + lc;
    const float* Wg = Wm + (size_t)(n0 + lrow) * ldw + lc;
    const uint32_t sAs = smem_u32(&As[0][0]);
    const uint32_t sWs = smem_u32(&Ws[0][0]);
    const uint32_t soff = (uint32_t)(lrow * SST + lc) * 4u;

    const int NK = K / BK;

    // prefetch tile 0
    {
        cp_async16(sAs + soff,      Ag);
        cp_async16(sAs + soff + 16, Ag + 4);
        cp_async16(sWs + soff,      Wg);
        cp_async16(sWs + soff + 16, Wg + 4);
        asm volatile("cp.async.commit_group;");
    }

    float acc[4][4][4];
#pragma unroll
    for (int i = 0; i < 4; i++)
#pragma unroll
        for (int j = 0; j < 4; j++)
#pragma unroll
            for (int q = 0; q < 4; q++) acc[i][j][q] = 0.0f;

    const int fr = lane >> 2;   // 0..7
    const int fc = lane & 3;    // 0..3

    for (int it = 0; it < NK; it++) {
        const int buf = it & 1;

        if (it + 1 < NK) {
            const uint32_t dst = (it + 1) & 1;
            const float* Ap = Ag + (size_t)(it + 1) * BK;
            const float* Wp = Wg + (size_t)(it + 1) * BK;
            cp_async16(sAs + dst * (BM * SST * 4) + soff,      Ap);
            cp_async16(sAs + dst * (BM * SST * 4) + soff + 16, Ap + 4);
            cp_async16(sWs + dst * (BN * SST * 4) + soff,      Wp);
            cp_async16(sWs + dst * (BN * SST * 4) + soff + 16, Wp + 4);
            asm volatile("cp.async.commit_group;");
            asm volatile("cp.async.wait_group 1;");
        } else {
            asm volatile("cp.async.wait_group 0;");
        }
        __syncthreads();

        const float* Ab = &As[buf][0];
        const float* Wb = &Ws[buf][0];

#pragma unroll
        for (int k8 = 0; k8 < 2; k8++) {
            const int kb = k8 * 8;

            // B fragments: hi/lo for all 4 j-atoms (8 elems -> 16 regs)
            uint32_t bh[4][2], bl[4][2];
#pragma unroll
            for (int j = 0; j < 4; j++) {
                const int nb = warp_n + j * 8;
                float b0 = Wb[(nb + fr) * SST + kb + fc];
                float b1 = Wb[(nb + fr) * SST + kb + fc + 4];
                tf32_split(b0, bh[j][0], bl[j][0]);
                tf32_split(b1, bh[j][1], bl[j][1]);
            }

#pragma unroll
            for (int i = 0; i < 4; i++) {
                const int mb = warp_m + i * 16;
                float a0 = Ab[(mb + fr)     * SST + kb + fc];
                float a1 = Ab[(mb + fr + 8) * SST + kb + fc];
                float a2 = Ab[(mb + fr)     * SST + kb + fc + 4];
                float a3 = Ab[(mb + fr + 8) * SST + kb + fc + 4];
                uint32_t ah[4], al[4];
                tf32_split(a0, ah[0], al[0]);
                tf32_split(a1, ah[1], al[1]);
                tf32_split(a2, ah[2], al[2]);
                tf32_split(a3, ah[3], al[3]);

#pragma unroll
                for (int j = 0; j < 4; j++) {
                    // hi*hi
                    mma_tf32(acc[i][j][0], acc[i][j][1], acc[i][j][2], acc[i][j][3],
                             ah[0], ah[1], ah[2], ah[3], bh[j][0], bh[j][1]);
                    // hi*lo
                    mma_tf32(acc[i][j][0], acc[i][j][1], acc[i][j][2], acc[i][j][3],
                             ah[0], ah[1], ah[2], ah[3], bl[j][0], bl[j][1]);
                    // lo*hi
                    mma_tf32(acc[i][j][0], acc[i][j][1], acc[i][j][2], acc[i][j][3],
                             al[0], al[1], al[2], al[3], bh[j][0], bh[j][1]);
                }
            }
        }
        __syncthreads();
    }

    // epilogue: bias + store
#pragma unroll
    for (int j = 0; j < 4; j++) {
        const int ncol = n0 + warp_n + j * 8 + fc * 2;
        const float2 bv = *reinterpret_cast<const float2*>(&bias[ncol]);
#pragma unroll
        for (int i = 0; i < 4; i++) {
            const int r0 = m0 + warp_m + i * 16 + fr;
            float2 v0, v1;
            v0.x = acc[i][j][0] + bv.x; v0.y = acc[i][j][1] + bv.y;
            v1.x = acc[i][j][2] + bv.x; v1.y = acc[i][j][3] + bv.y;
            *reinterpret_cast<float2*>(&C[(size_t)r0 * ldc + ncol])       = v0;
            *reinterpret_cast<float2*>(&C[(size_t)(r0 + 8) * ldc + ncol]) = v1;
        }
    }
}

// ===========================================================================
// Grid-wide barrier (128 co-resident blocks)
// ===========================================================================
__device__ __forceinline__ void grid_barrier()
{
    __syncthreads();
    if (threadIdx.x == 0) {
        __threadfence();
        unsigned gen = *(volatile unsigned*)&g_gen;
        unsigned arrived = atomicAdd(&g_cnt, 1u);
        if (arrived == gridDim.x - 1) {
            *(volatile unsigned*)&g_cnt = 0u;
            __threadfence();
            atomicAdd(&g_gen, 1u);
        } else {
            while (*(volatile unsigned*)&g_gen == gen) { __nanosleep(64); }
        }
        __threadfence();
    }
    __syncthreads();
}

// ===========================================================================
// Persistent recurrence (unchanged from R2)
// ===========================================================================
__global__ __launch_bounds__(256) void rnn_scan_k(
    const float* __restrict__ h0, const float* __restrict__ Wi2h)
{
    extern __shared__ float sm[];
    float* wsh = sm;
    float* hsh = sm + KC * JT;

    const int tid = threadIdx.x;
    const int bid = blockIdx.x;
    const int c   = bid >> 4;
    const int jt  = bid & 15;
    const int j0  = jt * JT;
    const int k0  = c * KC;

    for (int idx = tid; idx < JT * KC; idx += 256) {
        int j = idx / KC, k = idx % KC;
        wsh[k * JT + j] = Wi2h[(size_t)(j0 + j) * (NIN + HID) + NIN + k0 + k];
    }

    const int tb = tid >> 4;
    const int tj = tid & 15;

    for (int t = 0; t < T_STEPS; t++) {
        const float* hprev = (t == 0) ? h0 : (g_UH + (size_t)(t - 1) * BSZ * HID);

        for (int idx = tid; idx < BSZ * KC; idx += 256) {
            int b = idx >> 7;
            int k = idx & (KC - 1);
            hsh[k * 65 + b] = hprev[b * HID + k0 + k];
        }
        __syncthreads();

        float acc[4][4];
#pragma unroll
        for (int i = 0; i < 4; i++)
#pragma unroll
            for (int j = 0; j < 4; j++) acc[i][j] = 0.0f;

#pragma unroll 8
        for (int kk = 0; kk < KC; kk++) {
            float a0 = hsh[kk * 65 + tb * 4 + 0];
            float a1 = hsh[kk * 65 + tb * 4 + 1];
            float a2 = hsh[kk * 65 + tb * 4 + 2];
            float a3 = hsh[kk * 65 + tb * 4 + 3];
            float w0 = wsh[kk * JT + tj * 4 + 0];
            float w1 = wsh[kk * JT + tj * 4 + 1];
            float w2 = wsh[kk * JT + tj * 4 + 2];
            float w3 = wsh[kk * JT + tj * 4 + 3];
            acc[0][0] = fmaf(a0, w0, acc[0][0]); acc[0][1] = fmaf(a0, w1, acc[0][1]);
            acc[0][2] = fmaf(a0, w2, acc[0][2]); acc[0][3] = fmaf(a0, w3, acc[0][3]);
            acc[1][0] = fmaf(a1, w0, acc[1][0]); acc[1][1] = fmaf(a1, w1, acc[1][1]);
            acc[1][2] = fmaf(a1, w2, acc[1][2]); acc[1][3] = fmaf(a1, w3, acc[1][3]);
            acc[2][0] = fmaf(a2, w0, acc[2][0]); acc[2][1] = fmaf(a2, w1, acc[2][1]);
            acc[2][2] = fmaf(a2, w2, acc[2][2]); acc[2][3] = fmaf(a2, w3, acc[2][3]);
            acc[3][0] = fmaf(a3, w0, acc[3][0]); acc[3][1] = fmaf(a3, w1, acc[3][1]);
            acc[3][2] = fmaf(a3, w2, acc[3][2]); acc[3][3] = fmaf(a3, w3, acc[3][3]);
        }

#pragma unroll
        for (int i = 0; i < 4; i++) {
            float4 v;
            v.x = acc[i][0]; v.y = acc[i][1]; v.z = acc[i][2]; v.w = acc[i][3];
            *reinterpret_cast<float4*>(
                &g_part[(size_t)(c * BSZ + tb * 4 + i) * HID + j0 + tj * 4]) = v;
        }

        grid_barrier();

        {
            const int base = bid * ((BSZ * HID) / RNN_BLOCKS);
            for (int l = tid; l < (BSZ * HID) / RNN_BLOCKS; l += 256) {
                int idx = base + l;
                int b = idx >> 10;
                int j = idx & (HID - 1);
                size_t uoff = ((size_t)t * BSZ + b) * HID + j;
                float v = g_UH[uoff];
#pragma unroll
                for (int cc = 0; cc < NC; cc++)
                    v += g_part[(size_t)(cc * BSZ + b) * HID + j];
                g_UH[uoff] = tanhf(v);
            }
        }

        grid_barrier();
    }
}

// ===========================================================================
extern "C" void kernel_launch(void* const* d_in, const int* in_sizes, int n_in,
                              void* d_out, int out_size)
{
    (void)in_sizes; (void)n_in; (void)out_size;
    const float* x     = (const float*)d_in[0];
    const float* h0    = (const float*)d_in[1];
    const float* W_i2h = (const float*)d_in[2];
    const float* b_i2h = (const float*)d_in[3];
    const float* W_h2o = (const float*)d_in[4];
    const float* b_h2o = (const float*)d_in[5];
    float* out = (float*)d_out;

    float* uh = nullptr;
    cudaGetSymbolAddress((void**)&uh, g_UH);

    // 1) U = X @ Wx^T + b_i2h   (3xTF32 mma.sync)
    dim3 g1(HID / BN, (T_STEPS * BSZ) / BM);
    gemm_mma_k<<<g1, 256>>>(x, NIN, W_i2h, NIN + HID, b_i2h, uh, HID, NIN);

    // 2) sequential recurrence (persistent, fp32 SIMT)
    int smem = (KC * JT + KC * 65) * (int)sizeof(float);
    cudaFuncSetAttribute(rnn_scan_k, cudaFuncAttributeMaxDynamicSharedMemorySize, smem);
    rnn_scan_k<<<RNN_BLOCKS, 256, smem>>>(h0, W_i2h);

    // 3) out = H @ W_h2o^T + b_h2o   (3xTF32 mma.sync)
    dim3 g3(NOUT / BN, (T_STEPS * BSZ) / BM);
    gemm_mma_k<<<g3, 256>>>(uh, HID, W_h2o, HID, b_h2o, out, NOUT, HID);
}

// round 6
// speedup vs baseline: 1.1855x; 1.0555x over previous
#include <cuda_runtime.h>
#include <cstdint>

#define T_STEPS 512
#define BSZ     64
#define NIN     1024
#define HID     1024
#define NOUT    1024

// recurrence partition
#define NC       8
#define KC       128
#define JT       64
#define RNN_BLOCKS 128

// scratch
__device__ float   g_UH[(size_t)T_STEPS * BSZ * HID];
__device__ float   g_part[NC * BSZ * HID];
__device__ unsigned g_cnt;
__device__ unsigned g_gen;

// ===========================================================================
// 3xTF32 mma.sync GEMM (unchanged from R5 — known good, ~1.07ms each)
// ===========================================================================
#define BM 128
#define BN 128
#define BK 16
#define SST 20

__device__ __forceinline__ void cp_async16(uint32_t smem_addr, const void* gptr) {
    asm volatile("cp.async.cg.shared.global [%0], [%1], 16;"
                 :: "r"(smem_addr), "l"(gptr));
}
__device__ __forceinline__ uint32_t smem_u32(const void* p) {
    uint32_t a;
    asm("{ .reg .u64 t; cvta.to.shared.u64 t, %1; cvt.u32.u64 %0, t; }"
        : "=r"(a) : "l"(p));
    return a;
}
__device__ __forceinline__ uint32_t f2tf32(float v) {
    uint32_t r;
    asm("cvt.rna.tf32.f32 %0, %1;" : "=r"(r) : "f"(v));
    return r;
}
__device__ __forceinline__ void tf32_split(float x, uint32_t& hi, uint32_t& lo) {
    hi = f2tf32(x);
    lo = f2tf32(x - __uint_as_float(hi));
}
__device__ __forceinline__ void mma_tf32(
    float& d0, float& d1, float& d2, float& d3,
    uint32_t a0, uint32_t a1, uint32_t a2, uint32_t a3,
    uint32_t b0, uint32_t b1)
{
    asm volatile(
        "mma.sync.aligned.m16n8k8.row.col.f32.tf32.tf32.f32 "
        "{%0,%1,%2,%3}, {%4,%5,%6,%7}, {%8,%9}, {%0,%1,%2,%3};"
        : "+f"(d0), "+f"(d1), "+f"(d2), "+f"(d3)
        : "r"(a0), "r"(a1), "r"(a2), "r"(a3), "r"(b0), "r"(b1));
}

__global__ __launch_bounds__(256) void gemm_mma_k(
    const float* __restrict__ A, int lda,
    const float* __restrict__ Wm, int ldw,
    const float* __restrict__ bias,
    float* __restrict__ C, int ldc, int K)
{
    __shared__ float As[2][BM * SST];
    __shared__ float Ws[2][BN * SST];

    const int tid = threadIdx.x;
    const int wid = tid >> 5;
    const int lane = tid & 31;
    const int m0 = blockIdx.y * BM;
    const int n0 = blockIdx.x * BN;

    const int warp_m = (wid >> 2) * 64;
    const int warp_n = (wid & 3) * 32;

    const int lrow = tid >> 1;
    const int lc   = (tid & 1) * 8;
    const float* Ag = A  + (size_t)(m0 + lrow) * lda + lc;
    const float* Wg = Wm + (size_t)(n0 + lrow) * ldw + lc;
    const uint32_t sAs = smem_u32(&As[0][0]);
    const uint32_t sWs = smem_u32(&Ws[0][0]);
    const uint32_t soff = (uint32_t)(lrow * SST + lc) * 4u;

    const int NK = K / BK;

    {
        cp_async16(sAs + soff,      Ag);
        cp_async16(sAs + soff + 16, Ag + 4);
        cp_async16(sWs + soff,      Wg);
        cp_async16(sWs + soff + 16, Wg + 4);
        asm volatile("cp.async.commit_group;");
    }

    float acc[4][4][4];
#pragma unroll
    for (int i = 0; i < 4; i++)
#pragma unroll
        for (int j = 0; j < 4; j++)
#pragma unroll
            for (int q = 0; q < 4; q++) acc[i][j][q] = 0.0f;

    const int fr = lane >> 2;
    const int fc = lane & 3;

    for (int it = 0; it < NK; it++) {
        const int buf = it & 1;

        if (it + 1 < NK) {
            const uint32_t dst = (it + 1) & 1;
            const float* Ap = Ag + (size_t)(it + 1) * BK;
            const float* Wp = Wg + (size_t)(it + 1) * BK;
            cp_async16(sAs + dst * (BM * SST * 4) + soff,      Ap);
            cp_async16(sAs + dst * (BM * SST * 4) + soff + 16, Ap + 4);
            cp_async16(sWs + dst * (BN * SST * 4) + soff,      Wp);
            cp_async16(sWs + dst * (BN * SST * 4) + soff + 16, Wp + 4);
            asm volatile("cp.async.commit_group;");
            asm volatile("cp.async.wait_group 1;");
        } else {
            asm volatile("cp.async.wait_group 0;");
        }
        __syncthreads();

        const float* Ab = &As[buf][0];
        const float* Wb = &Ws[buf][0];

#pragma unroll
        for (int k8 = 0; k8 < 2; k8++) {
            const int kb = k8 * 8;

            uint32_t bh[4][2], bl[4][2];
#pragma unroll
            for (int j = 0; j < 4; j++) {
                const int nb = warp_n + j * 8;
                float b0 = Wb[(nb + fr) * SST + kb + fc];
                float b1 = Wb[(nb + fr) * SST + kb + fc + 4];
                tf32_split(b0, bh[j][0], bl[j][0]);
                tf32_split(b1, bh[j][1], bl[j][1]);
            }

#pragma unroll
            for (int i = 0; i < 4; i++) {
                const int mb = warp_m + i * 16;
                float a0 = Ab[(mb + fr)     * SST + kb + fc];
                float a1 = Ab[(mb + fr + 8) * SST + kb + fc];
                float a2 = Ab[(mb + fr)     * SST + kb + fc + 4];
                float a3 = Ab[(mb + fr + 8) * SST + kb + fc + 4];
                uint32_t ah[4], al[4];
                tf32_split(a0, ah[0], al[0]);
                tf32_split(a1, ah[1], al[1]);
                tf32_split(a2, ah[2], al[2]);
                tf32_split(a3, ah[3], al[3]);

#pragma unroll
                for (int j = 0; j < 4; j++) {
                    mma_tf32(acc[i][j][0], acc[i][j][1], acc[i][j][2], acc[i][j][3],
                             ah[0], ah[1], ah[2], ah[3], bh[j][0], bh[j][1]);
                    mma_tf32(acc[i][j][0], acc[i][j][1], acc[i][j][2], acc[i][j][3],
                             ah[0], ah[1], ah[2], ah[3], bl[j][0], bl[j][1]);
                    mma_tf32(acc[i][j][0], acc[i][j][1], acc[i][j][2], acc[i][j][3],
                             al[0], al[1], al[2], al[3], bh[j][0], bh[j][1]);
                }
            }
        }
        __syncthreads();
    }

#pragma unroll
    for (int j = 0; j < 4; j++) {
        const int ncol = n0 + warp_n + j * 8 + fc * 2;
        const float2 bv = *reinterpret_cast<const float2*>(&bias[ncol]);
#pragma unroll
        for (int i = 0; i < 4; i++) {
            const int r0 = m0 + warp_m + i * 16 + fr;
            float2 v0, v1;
            v0.x = acc[i][j][0] + bv.x; v0.y = acc[i][j][1] + bv.y;
            v1.x = acc[i][j][2] + bv.x; v1.y = acc[i][j][3] + bv.y;
            *reinterpret_cast<float2*>(&C[(size_t)r0 * ldc + ncol])       = v0;
            *reinterpret_cast<float2*>(&C[(size_t)(r0 + 8) * ldc + ncol]) = v1;
        }
    }
}

// ===========================================================================
// Fast grid barrier: scoped atomics, no membar.gpu, no nanosleep.
// Arrive: atom.acq_rel.gpu (RMW chain gives transitive release sequence).
// Release: red.release.gpu on generation. Spin: ld.acquire.gpu.
// All cross-SM data uses .cg (L2) so no stale-L1 hazard.
// ===========================================================================
__device__ __forceinline__ void grid_barrier_fast()
{
    __syncthreads();
    if (threadIdx.x == 0) {
        unsigned gen;
        asm volatile("ld.acquire.gpu.global.u32 %0, [%1];"
                     : "=r"(gen) : "l"(&g_gen));
        unsigned old;
        asm volatile("atom.acq_rel.gpu.global.add.u32 %0, [%1], 1;"
                     : "=r"(old) : "l"(&g_cnt));
        if (old == gridDim.x - 1) {
            asm volatile("st.relaxed.gpu.global.u32 [%0], 0;"
                         :: "l"(&g_cnt));
            asm volatile("red.release.gpu.global.add.u32 [%0], 1;"
                         :: "l"(&g_gen));
        } else {
            unsigned cur;
            do {
                asm volatile("ld.acquire.gpu.global.u32 %0, [%1];"
                             : "=r"(cur) : "l"(&g_gen));
            } while (cur == gen);
        }
    }
    __syncthreads();
}

// ===========================================================================
// Persistent recurrence: .cg data paths + cheap barriers + U prefetch.
// ===========================================================================
__global__ __launch_bounds__(256) void rnn_scan_k(
    const float* __restrict__ h0, const float* __restrict__ Wi2h)
{
    extern __shared__ float sm[];
    float* wsh = sm;
    float* hsh = sm + KC * JT;

    const int tid = threadIdx.x;
    const int bid = blockIdx.x;
    const int c   = bid >> 4;
    const int jt  = bid & 15;
    const int j0  = jt * JT;
    const int k0  = c * KC;

    for (int idx = tid; idx < JT * KC; idx += 256) {
        int j = idx / KC, k = idx % KC;
        wsh[k * JT + j] = Wi2h[(size_t)(j0 + j) * (NIN + HID) + NIN + k0 + k];
    }

    const int tb = tid >> 4;
    const int tj = tid & 15;

    // Phase B ownership: 512 contiguous elements of (b,j) flat space, 2/thread
    const int pb_base = bid * ((BSZ * HID) / RNN_BLOCKS);  // bid*512
    const int pb_i0 = pb_base + tid;
    const int pb_i1 = pb_base + tid + 256;
    const int pb_b0 = pb_i0 >> 10, pb_j0 = pb_i0 & (HID - 1);
    const int pb_b1 = pb_i1 >> 10, pb_j1 = pb_i1 & (HID - 1);

    for (int t = 0; t < T_STEPS; t++) {
        const float* hprev = (t == 0) ? h0 : (g_UH + (size_t)(t - 1) * BSZ * HID);

        // stage h chunk (L2 path — written via stcg by other blocks last step)
        for (int idx = tid; idx < BSZ * KC; idx += 256) {
            int b = idx >> 7;
            int k = idx & (KC - 1);
            hsh[k * 65 + b] = __ldcg(&hprev[b * HID + k0 + k]);
        }
        __syncthreads();

        float acc[4][4];
#pragma unroll
        for (int i = 0; i < 4; i++)
#pragma unroll
            for (int j = 0; j < 4; j++) acc[i][j] = 0.0f;

#pragma unroll 8
        for (int kk = 0; kk < KC; kk++) {
            float a0 = hsh[kk * 65 + tb * 4 + 0];
            float a1 = hsh[kk * 65 + tb * 4 + 1];
            float a2 = hsh[kk * 65 + tb * 4 + 2];
            float a3 = hsh[kk * 65 + tb * 4 + 3];
            float w0 = wsh[kk * JT + tj * 4 + 0];
            float w1 = wsh[kk * JT + tj * 4 + 1];
            float w2 = wsh[kk * JT + tj * 4 + 2];
            float w3 = wsh[kk * JT + tj * 4 + 3];
            acc[0][0] = fmaf(a0, w0, acc[0][0]); acc[0][1] = fmaf(a0, w1, acc[0][1]);
            acc[0][2] = fmaf(a0, w2, acc[0][2]); acc[0][3] = fmaf(a0, w3, acc[0][3]);
            acc[1][0] = fmaf(a1, w0, acc[1][0]); acc[1][1] = fmaf(a1, w1, acc[1][1]);
            acc[1][2] = fmaf(a1, w2, acc[1][2]); acc[1][3] = fmaf(a1, w3, acc[1][3]);
            acc[2][0] = fmaf(a2, w0, acc[2][0]); acc[2][1] = fmaf(a2, w1, acc[2][1]);
            acc[2][2] = fmaf(a2, w2, acc[2][2]); acc[2][3] = fmaf(a2, w3, acc[2][3]);
            acc[3][0] = fmaf(a3, w0, acc[3][0]); acc[3][1] = fmaf(a3, w1, acc[3][1]);
            acc[3][2] = fmaf(a3, w2, acc[3][2]); acc[3][3] = fmaf(a3, w3, acc[3][3]);
        }

        // write partials (L2 path)
#pragma unroll
        for (int i = 0; i < 4; i++) {
            float4 v;
            v.x = acc[i][0]; v.y = acc[i][1]; v.z = acc[i][2]; v.w = acc[i][3];
            __stcg(reinterpret_cast<float4*>(
                &g_part[(size_t)(c * BSZ + tb * 4 + i) * HID + j0 + tj * 4]), v);
        }

        // prefetch U for Phase B before the barrier (step-independent data)
        const size_t u0 = ((size_t)t * BSZ + pb_b0) * HID + pb_j0;
        const size_t u1 = ((size_t)t * BSZ + pb_b1) * HID + pb_j1;
        float uv0 = __ldcg(&g_UH[u0]);
        float uv1 = __ldcg(&g_UH[u1]);

        grid_barrier_fast();

        // Phase B: reduce partials + U, tanh -> h_t (in place)
        {
            float v0 = uv0, v1 = uv1;
#pragma unroll
            for (int cc = 0; cc < NC; cc++) {
                v0 += __ldcg(&g_part[(size_t)(cc * BSZ + pb_b0) * HID + pb_j0]);
                v1 += __ldcg(&g_part[(size_t)(cc * BSZ + pb_b1) * HID + pb_j1]);
            }
            __stcg(&g_UH[u0], tanhf(v0));
            __stcg(&g_UH[u1], tanhf(v1));
        }

        grid_barrier_fast();
    }
}

// ===========================================================================
extern "C" void kernel_launch(void* const* d_in, const int* in_sizes, int n_in,
                              void* d_out, int out_size)
{
    (void)in_sizes; (void)n_in; (void)out_size;
    const float* x     = (const float*)d_in[0];
    const float* h0    = (const float*)d_in[1];
    const float* W_i2h = (const float*)d_in[2];
    const float* b_i2h = (const float*)d_in[3];
    const float* W_h2o = (const float*)d_in[4];
    const float* b_h2o = (const float*)d_in[5];
    float* out = (float*)d_out;

    float* uh = nullptr;
    cudaGetSymbolAddress((void**)&uh, g_UH);

    // 1) U = X @ Wx^T + b_i2h
    dim3 g1(HID / BN, (T_STEPS * BSZ) / BM);
    gemm_mma_k<<<g1, 256>>>(x, NIN, W_i2h, NIN + HID, b_i2h, uh, HID, NIN);

    // 2) sequential recurrence
    int smem = (KC * JT + KC * 65) * (int)sizeof(float);
    cudaFuncSetAttribute(rnn_scan_k, cudaFuncAttributeMaxDynamicSharedMemorySize, smem);
    rnn_scan_k<<<RNN_BLOCKS, 256, smem>>>(h0, W_i2h);

    // 3) out = H @ W_h2o^T + b_h2o
    dim3 g3(NOUT / BN, (T_STEPS * BSZ) / BM);
    gemm_mma_k<<<g3, 256>>>(uh, HID, W_h2o, HID, b_h2o, out, NOUT, HID);
}

// round 7
// speedup vs baseline: 1.5589x; 1.3150x over previous
#include <cuda_runtime.h>
#include <cstdint>

#define T_STEPS 512
#define BSZ     64
#define NIN     1024
#define HID     1024
#define NOUT    1024

// recurrence partition
#define NC       8
#define KC       128
#define JT       64
#define RNN_BLOCKS 128
#define SHS      132          // padded smem row stride (floats)

// scratch
__device__ float   g_UH[(size_t)T_STEPS * BSZ * HID];   // U -> h_t (fp32)
__device__ float   g_Hhi[BSZ * HID];                    // tf32-hi of current h
__device__ float   g_Hlo[BSZ * HID];                    // tf32-lo of current h
__device__ float   g_part[NC * BSZ * HID];
__device__ unsigned g_cnt;
__device__ unsigned g_gen;

// ===========================================================================
// common helpers
// ===========================================================================
__device__ __forceinline__ void cp_async16(uint32_t smem_addr, const void* gptr) {
    asm volatile("cp.async.cg.shared.global [%0], [%1], 16;"
                 :: "r"(smem_addr), "l"(gptr));
}
__device__ __forceinline__ uint32_t smem_u32(const void* p) {
    uint32_t a;
    asm("{ .reg .u64 t; cvta.to.shared.u64 t, %1; cvt.u32.u64 %0, t; }"
        : "=r"(a) : "l"(p));
    return a;
}
__device__ __forceinline__ uint32_t f2tf32(float v) {
    uint32_t r;
    asm("cvt.rna.tf32.f32 %0, %1;" : "=r"(r) : "f"(v));
    return r;
}
__device__ __forceinline__ void tf32_split(float x, uint32_t& hi, uint32_t& lo) {
    hi = f2tf32(x);
    lo = f2tf32(x - __uint_as_float(hi));
}
__device__ __forceinline__ void mma_tf32(
    float& d0, float& d1, float& d2, float& d3,
    uint32_t a0, uint32_t a1, uint32_t a2, uint32_t a3,
    uint32_t b0, uint32_t b1)
{
    asm volatile(
        "mma.sync.aligned.m16n8k8.row.col.f32.tf32.tf32.f32 "
        "{%0,%1,%2,%3}, {%4,%5,%6,%7}, {%8,%9}, {%0,%1,%2,%3};"
        : "+f"(d0), "+f"(d1), "+f"(d2), "+f"(d3)
        : "r"(a0), "r"(a1), "r"(a2), "r"(a3), "r"(b0), "r"(b1));
}

// ===========================================================================
// 3xTF32 mma.sync GEMM (unchanged — known good, ~1.07ms each)
// ===========================================================================
#define BM 128
#define BN 128
#define BK 16
#define SST 20

__global__ __launch_bounds__(256) void gemm_mma_k(
    const float* __restrict__ A, int lda,
    const float* __restrict__ Wm, int ldw,
    const float* __restrict__ bias,
    float* __restrict__ C, int ldc, int K)
{
    __shared__ float As[2][BM * SST];
    __shared__ float Ws[2][BN * SST];

    const int tid = threadIdx.x;
    const int wid = tid >> 5;
    const int lane = tid & 31;
    const int m0 = blockIdx.y * BM;
    const int n0 = blockIdx.x * BN;

    const int warp_m = (wid >> 2) * 64;
    const int warp_n = (wid & 3) * 32;

    const int lrow = tid >> 1;
    const int lc   = (tid & 1) * 8;
    const float* Ag = A  + (size_t)(m0 + lrow) * lda + lc;
    const float* Wg = Wm + (size_t)(n0 + lrow) * ldw + lc;
    const uint32_t sAs = smem_u32(&As[0][0]);
    const uint32_t sWs = smem_u32(&Ws[0][0]);
    const uint32_t soff = (uint32_t)(lrow * SST + lc) * 4u;

    const int NK = K / BK;

    {
        cp_async16(sAs + soff,      Ag);
        cp_async16(sAs + soff + 16, Ag + 4);
        cp_async16(sWs + soff,      Wg);
        cp_async16(sWs + soff + 16, Wg + 4);
        asm volatile("cp.async.commit_group;");
    }

    float acc[4][4][4];
#pragma unroll
    for (int i = 0; i < 4; i++)
#pragma unroll
        for (int j = 0; j < 4; j++)
#pragma unroll
            for (int q = 0; q < 4; q++) acc[i][j][q] = 0.0f;

    const int fr = lane >> 2;
    const int fc = lane & 3;

    for (int it = 0; it < NK; it++) {
        const int buf = it & 1;

        if (it + 1 < NK) {
            const uint32_t dst = (it + 1) & 1;
            const float* Ap = Ag + (size_t)(it + 1) * BK;
            const float* Wp = Wg + (size_t)(it + 1) * BK;
            cp_async16(sAs + dst * (BM * SST * 4) + soff,      Ap);
            cp_async16(sAs + dst * (BM * SST * 4) + soff + 16, Ap + 4);
            cp_async16(sWs + dst * (BN * SST * 4) + soff,      Wp);
            cp_async16(sWs + dst * (BN * SST * 4) + soff + 16, Wp + 4);
            asm volatile("cp.async.commit_group;");
            asm volatile("cp.async.wait_group 1;");
        } else {
            asm volatile("cp.async.wait_group 0;");
        }
        __syncthreads();

        const float* Ab = &As[buf][0];
        const float* Wb = &Ws[buf][0];

#pragma unroll
        for (int k8 = 0; k8 < 2; k8++) {
            const int kb = k8 * 8;

            uint32_t bh[4][2], bl[4][2];
#pragma unroll
            for (int j = 0; j < 4; j++) {
                const int nb = warp_n + j * 8;
                float b0 = Wb[(nb + fr) * SST + kb + fc];
                float b1 = Wb[(nb + fr) * SST + kb + fc + 4];
                tf32_split(b0, bh[j][0], bl[j][0]);
                tf32_split(b1, bh[j][1], bl[j][1]);
            }

#pragma unroll
            for (int i = 0; i < 4; i++) {
                const int mb = warp_m + i * 16;
                float a0 = Ab[(mb + fr)     * SST + kb + fc];
                float a1 = Ab[(mb + fr + 8) * SST + kb + fc];
                float a2 = Ab[(mb + fr)     * SST + kb + fc + 4];
                float a3 = Ab[(mb + fr + 8) * SST + kb + fc + 4];
                uint32_t ah[4], al[4];
                tf32_split(a0, ah[0], al[0]);
                tf32_split(a1, ah[1], al[1]);
                tf32_split(a2, ah[2], al[2]);
                tf32_split(a3, ah[3], al[3]);

#pragma unroll
                for (int j = 0; j < 4; j++) {
                    mma_tf32(acc[i][j][0], acc[i][j][1], acc[i][j][2], acc[i][j][3],
                             ah[0], ah[1], ah[2], ah[3], bh[j][0], bh[j][1]);
                    mma_tf32(acc[i][j][0], acc[i][j][1], acc[i][j][2], acc[i][j][3],
                             ah[0], ah[1], ah[2], ah[3], bl[j][0], bl[j][1]);
                    mma_tf32(acc[i][j][0], acc[i][j][1], acc[i][j][2], acc[i][j][3],
                             al[0], al[1], al[2], al[3], bh[j][0], bh[j][1]);
                }
            }
        }
        __syncthreads();
    }

#pragma unroll
    for (int j = 0; j < 4; j++) {
        const int ncol = n0 + warp_n + j * 8 + fc * 2;
        const float2 bv = *reinterpret_cast<const float2*>(&bias[ncol]);
#pragma unroll
        for (int i = 0; i < 4; i++) {
            const int r0 = m0 + warp_m + i * 16 + fr;
            float2 v0, v1;
            v0.x = acc[i][j][0] + bv.x; v0.y = acc[i][j][1] + bv.y;
            v1.x = acc[i][j][2] + bv.x; v1.y = acc[i][j][3] + bv.y;
            *reinterpret_cast<float2*>(&C[(size_t)r0 * ldc + ncol])       = v0;
            *reinterpret_cast<float2*>(&C[(size_t)(r0 + 8) * ldc + ncol]) = v1;
        }
    }
}

// ===========================================================================
// Fast grid barrier (unchanged from R6)
// ===========================================================================
__device__ __forceinline__ void grid_barrier_fast()
{
    __syncthreads();
    if (threadIdx.x == 0) {
        unsigned gen;
        asm volatile("ld.acquire.gpu.global.u32 %0, [%1];"
                     : "=r"(gen) : "l"(&g_gen));
        unsigned old;
        asm volatile("atom.acq_rel.gpu.global.add.u32 %0, [%1], 1;"
                     : "=r"(old) : "l"(&g_cnt));
        if (old == gridDim.x - 1) {
            asm volatile("st.relaxed.gpu.global.u32 [%0], 0;"
                         :: "l"(&g_cnt));
            asm volatile("red.release.gpu.global.add.u32 [%0], 1;"
                         :: "l"(&g_gen));
        } else {
            unsigned cur;
            do {
                asm volatile("ld.acquire.gpu.global.u32 %0, [%1];"
                             : "=r"(cur) : "l"(&g_gen));
            } while (cur == gen);
        }
    }
    __syncthreads();
}

// ===========================================================================
// Persistent recurrence, tensor-core Phase A (3xTF32, W-frags in registers).
// Block (c, jt): Phase A = h[64, KC] @ W[JT, KC]^T via mma m16n8k8.
// 8 warps: (mh 0..1) x (nw 0..3); warp tile = 32(m) x 16(n).
// h staged pre-split (hi/lo) into smem, stride SHS=132 (conflict-free frags).
// ===========================================================================
__global__ __launch_bounds__(256) void rnn_scan_k(
    const float* __restrict__ h0, const float* __restrict__ Wi2h)
{
    extern __shared__ float sm[];
    float* sh_hi = sm;                 // [64][SHS]
    float* sh_lo = sm + 64 * SHS;      // [64][SHS]

    const int tid = threadIdx.x;
    const int bid = blockIdx.x;
    const int wid = tid >> 5;
    const int lane = tid & 31;
    const int c   = bid >> 4;          // k-chunk
    const int jt  = bid & 15;
    const int j0  = jt * JT;
    const int k0  = c * KC;

    const int mh = wid >> 2;           // 0/1 -> m base 0/32
    const int nw = wid & 3;            // n base = j0 + nw*16
    const int fr = lane >> 2;
    const int fc = lane & 3;

    // --- preload W fragments (loop-invariant): 2 n-tiles x 16 k8, hi+lo ---
    uint32_t Wh[2][16][2], Wl[2][16][2];
#pragma unroll
    for (int nj = 0; nj < 2; nj++) {
        const int n = j0 + nw * 16 + nj * 8 + fr;
        const float* wr = &Wi2h[(size_t)n * (NIN + HID) + NIN + k0];
#pragma unroll
        for (int ks = 0; ks < 16; ks++) {
            tf32_split(wr[ks * 8 + fc],     Wh[nj][ks][0], Wl[nj][ks][0]);
            tf32_split(wr[ks * 8 + fc + 4], Wh[nj][ks][1], Wl[nj][ks][1]);
        }
    }

    // Phase B ownership: 512 elements, 2/thread; flat idx = b*1024 + j
    const int pb_i0 = bid * 512 + tid;
    const int pb_i1 = bid * 512 + tid + 256;
    const int pb_b0 = pb_i0 >> 10, pb_j0 = pb_i0 & (HID - 1);
    const int pb_b1 = pb_i1 >> 10, pb_j1 = pb_i1 & (HID - 1);

    for (int t = 0; t < T_STEPS; t++) {
        // --- stage h chunk (pre-split hi/lo), 8 float4 per thread per array ---
        if (t == 0) {
#pragma unroll
            for (int p = 0; p < 8; p++) {
                const int idx4 = tid + p * 256;          // 0..2047
                const int b = idx4 >> 5;
                const int kg = (idx4 & 31) * 4;
                float4 v = *reinterpret_cast<const float4*>(&h0[b * HID + k0 + kg]);
                uint32_t h0x, l0x, h1x, l1x, h2x, l2x, h3x, l3x;
                tf32_split(v.x, h0x, l0x); tf32_split(v.y, h1x, l1x);
                tf32_split(v.z, h2x, l2x); tf32_split(v.w, h3x, l3x);
                float4 hv, lv;
                hv.x = __uint_as_float(h0x); hv.y = __uint_as_float(h1x);
                hv.z = __uint_as_float(h2x); hv.w = __uint_as_float(h3x);
                lv.x = __uint_as_float(l0x); lv.y = __uint_as_float(l1x);
                lv.z = __uint_as_float(l2x); lv.w = __uint_as_float(l3x);
                *reinterpret_cast<float4*>(&sh_hi[b * SHS + kg]) = hv;
                *reinterpret_cast<float4*>(&sh_lo[b * SHS + kg]) = lv;
            }
        } else {
#pragma unroll
            for (int p = 0; p < 8; p++) {
                const int idx4 = tid + p * 256;
                const int b = idx4 >> 5;
                const int kg = (idx4 & 31) * 4;
                const int goff = b * HID + k0 + kg;
                float4 hv = __ldcg(reinterpret_cast<const float4*>(&g_Hhi[goff]));
                float4 lv = __ldcg(reinterpret_cast<const float4*>(&g_Hlo[goff]));
                *reinterpret_cast<float4*>(&sh_hi[b * SHS + kg]) = hv;
                *reinterpret_cast<float4*>(&sh_lo[b * SHS + kg]) = lv;
            }
        }
        __syncthreads();

        // --- Phase A: mma over 16 k8 steps ---
        float acc[2][2][4];
#pragma unroll
        for (int mi = 0; mi < 2; mi++)
#pragma unroll
            for (int nj = 0; nj < 2; nj++)
#pragma unroll
                for (int q = 0; q < 4; q++) acc[mi][nj][q] = 0.0f;

#pragma unroll
        for (int ks = 0; ks < 16; ks++) {
            const int kk = ks * 8 + fc;
            uint32_t ahi[2][4], alo[2][4];
#pragma unroll
            for (int mi = 0; mi < 2; mi++) {
                const int r0 = (mh * 32 + mi * 16 + fr) * SHS;
                const int r8 = r0 + 8 * SHS;
                ahi[mi][0] = __float_as_uint(sh_hi[r0 + kk]);
                ahi[mi][1] = __float_as_uint(sh_hi[r8 + kk]);
                ahi[mi][2] = __float_as_uint(sh_hi[r0 + kk + 4]);
                ahi[mi][3] = __float_as_uint(sh_hi[r8 + kk + 4]);
                alo[mi][0] = __float_as_uint(sh_lo[r0 + kk]);
                alo[mi][1] = __float_as_uint(sh_lo[r8 + kk]);
                alo[mi][2] = __float_as_uint(sh_lo[r0 + kk + 4]);
                alo[mi][3] = __float_as_uint(sh_lo[r8 + kk + 4]);
            }
#pragma unroll
            for (int mi = 0; mi < 2; mi++)
#pragma unroll
                for (int nj = 0; nj < 2; nj++) {
                    mma_tf32(acc[mi][nj][0], acc[mi][nj][1], acc[mi][nj][2], acc[mi][nj][3],
                             ahi[mi][0], ahi[mi][1], ahi[mi][2], ahi[mi][3],
                             Wh[nj][ks][0], Wh[nj][ks][1]);
                    mma_tf32(acc[mi][nj][0], acc[mi][nj][1], acc[mi][nj][2], acc[mi][nj][3],
                             ahi[mi][0], ahi[mi][1], ahi[mi][2], ahi[mi][3],
                             Wl[nj][ks][0], Wl[nj][ks][1]);
                    mma_tf32(acc[mi][nj][0], acc[mi][nj][1], acc[mi][nj][2], acc[mi][nj][3],
                             alo[mi][0], alo[mi][1], alo[mi][2], alo[mi][3],
                             Wh[nj][ks][0], Wh[nj][ks][1]);
                }
        }

        // --- write partials (c-frag layout) ---
#pragma unroll
        for (int mi = 0; mi < 2; mi++) {
            const int b0 = mh * 32 + mi * 16 + fr;
#pragma unroll
            for (int nj = 0; nj < 2; nj++) {
                const int n = j0 + nw * 16 + nj * 8 + fc * 2;
                float2 v0, v1;
                v0.x = acc[mi][nj][0]; v0.y = acc[mi][nj][1];
                v1.x = acc[mi][nj][2]; v1.y = acc[mi][nj][3];
                __stcg(reinterpret_cast<float2*>(
                    &g_part[(size_t)(c * BSZ + b0) * HID + n]), v0);
                __stcg(reinterpret_cast<float2*>(
                    &g_part[(size_t)(c * BSZ + b0 + 8) * HID + n]), v1);
            }
        }

        // prefetch U before barrier
        const size_t u0 = ((size_t)t * BSZ + pb_b0) * HID + pb_j0;
        const size_t u1 = ((size_t)t * BSZ + pb_b1) * HID + pb_j1;
        float uv0 = __ldcg(&g_UH[u0]);
        float uv1 = __ldcg(&g_UH[u1]);

        grid_barrier_fast();

        // --- Phase B: reduce + tanh, write h (fp32) and pre-split hi/lo ---
        {
            float v0 = uv0, v1 = uv1;
#pragma unroll
            for (int cc = 0; cc < NC; cc++) {
                v0 += __ldcg(&g_part[(size_t)(cc * BSZ + pb_b0) * HID + pb_j0]);
                v1 += __ldcg(&g_part[(size_t)(cc * BSZ + pb_b1) * HID + pb_j1]);
            }
            v0 = tanhf(v0);
            v1 = tanhf(v1);
            __stcg(&g_UH[u0], v0);
            __stcg(&g_UH[u1], v1);
            uint32_t h0b, l0b, h1b, l1b;
            tf32_split(v0, h0b, l0b);
            tf32_split(v1, h1b, l1b);
            __stcg(&g_Hhi[pb_i0], __uint_as_float(h0b));
            __stcg(&g_Hlo[pb_i0], __uint_as_float(l0b));
            __stcg(&g_Hhi[pb_i1], __uint_as_float(h1b));
            __stcg(&g_Hlo[pb_i1], __uint_as_float(l1b));
        }

        grid_barrier_fast();
    }
}

// ===========================================================================
extern "C" void kernel_launch(void* const* d_in, const int* in_sizes, int n_in,
                              void* d_out, int out_size)
{
    (void)in_sizes; (void)n_in; (void)out_size;
    const float* x     = (const float*)d_in[0];
    const float* h0    = (const float*)d_in[1];
    const float* W_i2h = (const float*)d_in[2];
    const float* b_i2h = (const float*)d_in[3];
    const float* W_h2o = (const float*)d_in[4];
    const float* b_h2o = (const float*)d_in[5];
    float* out = (float*)d_out;

    float* uh = nullptr;
    cudaGetSymbolAddress((void**)&uh, g_UH);

    // 1) U = X @ Wx^T + b_i2h
    dim3 g1(HID / BN, (T_STEPS * BSZ) / BM);
    gemm_mma_k<<<g1, 256>>>(x, NIN, W_i2h, NIN + HID, b_i2h, uh, HID, NIN);

    // 2) sequential recurrence (tensor-core Phase A)
    int smem = 2 * 64 * SHS * (int)sizeof(float);   // ~67.6 KB
    cudaFuncSetAttribute(rnn_scan_k, cudaFuncAttributeMaxDynamicSharedMemorySize, smem);
    rnn_scan_k<<<RNN_BLOCKS, 256, smem>>>(h0, W_i2h);

    // 3) out = H @ W_h2o^T + b_h2o
    dim3 g3(NOUT / BN, (T_STEPS * BSZ) / BM);
    gemm_mma_k<<<g3, 256>>>(uh, HID, W_h2o, HID, b_h2o, out, NOUT, HID);
}